// round 5
// baseline (speedup 1.0000x reference)
#include <cuda_runtime.h>
#include <cuda_bf16.h>
#include <math_constants.h>

#define N 8192
#define D 64
#define LOG2E 1.4426950408889634f

// ---------------- scratch (static device memory; no allocation) ----------------
__device__ float g_Qx[N * D];
__device__ float g_Kx[N * D];
__device__ float g_Qy[N * D];
__device__ float g_Ky[N * D];
__device__ float g_xatt[N * D];
__device__ float g_yatt[N * D];
__device__ float g_xnrm[N];
__device__ float g_ynrm[N];

// ---------------- packed f32x2 helpers ----------------
__device__ __forceinline__ unsigned long long fma2_(unsigned long long a,
                                                    unsigned long long b,
                                                    unsigned long long c) {
    unsigned long long d;
    asm("fma.rn.f32x2 %0, %1, %2, %3;" : "=l"(d) : "l"(a), "l"(b), "l"(c));
    return d;
}
__device__ __forceinline__ unsigned long long mul2_(unsigned long long a,
                                                    unsigned long long b) {
    unsigned long long d;
    asm("mul.rn.f32x2 %0, %1, %2;" : "=l"(d) : "l"(a), "l"(b));
    return d;
}
__device__ __forceinline__ unsigned long long pk2(float lo, float hi) {
    unsigned long long r;
    asm("mov.b64 %0, {%1, %2};" : "=l"(r) : "f"(lo), "f"(hi));
    return r;
}
__device__ __forceinline__ float2 up2(unsigned long long v) {
    float lo, hi;
    asm("mov.b64 {%0, %1}, %2;" : "=f"(lo), "=f"(hi) : "l"(v));
    return make_float2(lo, hi);
}

// ---------------- kernel 1: projections Q = In@Wq * 0.125, K = In@Wk ----------------
// grid 4096 blocks x 256 threads; block handles 4 rows (covering x rows then y rows)
__global__ __launch_bounds__(256) void proj_kernel(const float* __restrict__ x,
                                                   const float* __restrict__ y,
                                                   const float* __restrict__ Wq,
                                                   const float* __restrict__ Wk) {
    __shared__ float sW[2][64][65];
    __shared__ float sIn[4][64];

    int tid = threadIdx.x;
    int base = blockIdx.x * 4;  // global row base (0..16380)

    const float* src;
    float *dstQ, *dstK;
    if (base < N) {
        src = x + (size_t)base * D;
        dstQ = g_Qx + (size_t)base * D;
        dstK = g_Kx + (size_t)base * D;
    } else {
        int b2 = base - N;
        src = y + (size_t)b2 * D;
        dstQ = g_Qy + (size_t)b2 * D;
        dstK = g_Ky + (size_t)b2 * D;
    }

    for (int idx = tid; idx < 4096; idx += 256) {
        sW[0][idx >> 6][idx & 63] = Wq[idx];
        sW[1][idx >> 6][idx & 63] = Wk[idx];
    }
    sIn[tid >> 6][tid & 63] = src[tid];
    __syncthreads();

    int j = tid & 63;
    int rl = tid >> 6;
    float fq = 0.f, fk = 0.f;
#pragma unroll
    for (int k = 0; k < 64; ++k) {
        float v = sIn[rl][k];
        fq = fmaf(v, sW[0][k][j], fq);
        fk = fmaf(v, sW[1][k][j], fk);
    }
    dstQ[rl * 64 + j] = fq * 0.125f;  // fold 1/sqrt(64)
    dstK[rl * 64 + j] = fk;
}

// ---------------- kernel 2: flash attention, fp32, f32x2 packed ----------------
// grid 256 blocks (0..127 = x-set, 128..255 = y-set), each block = 64 query rows.
// 256 threads: r = tid>>2 (query row 0..63), g = tid&3.
// Thread owns S columns c = g + 4*c' (c'=0..15)  -> 4 distinct banks across g.
// Thread owns O dims d = u*16 + g*4 (u=0..3)     -> 4 distinct banks across g.
__global__ __launch_bounds__(256, 2) void attn_kernel(const float* __restrict__ x,
                                                      const float* __restrict__ y) {
    __shared__ __align__(16) float Qs[64 * 68];
    __shared__ __align__(16) float Bs[64 * 68];  // K tile, then V tile (reused)

    int tid = threadIdx.x;
    int b = blockIdx.x;
    bool isx = b < 128;
    int bb = isx ? b : b - 128;
    int m0 = bb * 64;

    const float* Q = isx ? g_Qx : g_Qy;
    const float* K = isx ? g_Kx : g_Ky;
    const float* V = isx ? x : y;
    float* O = isx ? g_xatt : g_yatt;
    float* nrm = isx ? g_xnrm : g_ynrm;

    // load Q tile (row-major, stride 68)
    for (int t = tid; t < 1024; t += 256) {
        int row = t >> 4, u = t & 15;
        *(float4*)&Qs[row * 68 + u * 4] =
            *(const float4*)&Q[(size_t)(m0 + row) * 64 + u * 4];
    }

    int r = tid >> 2;
    int g = tid & 3;
    int lane = tid & 31;

    unsigned long long accd2[8];
#pragma unroll
    for (int u = 0; u < 8; ++u) accd2[u] = 0ull;
    float m_run = -CUDART_INF_F;
    float l_t = 0.f;

    for (int kt = 0; kt < 128; ++kt) {
        int n0 = kt * 64;
        __syncthreads();  // prev PV reads done
        for (int t = tid; t < 1024; t += 256) {
            int row = t >> 4, u = t & 15;
            *(float4*)&Bs[row * 68 + u * 4] =
                *(const float4*)&K[(size_t)(n0 + row) * 64 + u * 4];
        }
        __syncthreads();

        // ---- S = Q Kt^T (packed over k) ----
        unsigned long long sacc[16];
#pragma unroll
        for (int c = 0; c < 16; ++c) sacc[c] = 0ull;
        const float* qrow = &Qs[r * 68];
        const float* bbase = &Bs[g * 68];  // col row index = g + 4*c -> offset g*68 + c*272
#pragma unroll
        for (int kk = 0; kk < 64; kk += 4) {
            ulonglong2 q4 = *(const ulonglong2*)(qrow + kk);
#pragma unroll
            for (int c = 0; c < 16; ++c) {
                ulonglong2 kv = *(const ulonglong2*)(bbase + c * 272 + kk);
                sacc[c] = fma2_(q4.x, kv.x, sacc[c]);
                sacc[c] = fma2_(q4.y, kv.y, sacc[c]);
            }
        }
        float s[16];
#pragma unroll
        for (int c = 0; c < 16; ++c) {
            float2 v = up2(sacc[c]);
            s[c] = v.x + v.y;
        }

        // ---- online softmax (per-thread, row-max shared across the 4 lanes) ----
        float mt = s[0];
#pragma unroll
        for (int c = 1; c < 16; ++c) mt = fmaxf(mt, s[c]);
        mt = fmaxf(mt, __shfl_xor_sync(0xffffffffu, mt, 1));
        mt = fmaxf(mt, __shfl_xor_sync(0xffffffffu, mt, 2));
        float m_new = fmaxf(m_run, mt);
        float scale = exp2f((m_run - m_new) * LOG2E);
        l_t *= scale;
        unsigned long long sc2 = pk2(scale, scale);
#pragma unroll
        for (int u = 0; u < 8; ++u) accd2[u] = mul2_(accd2[u], sc2);
        float p[16];
#pragma unroll
        for (int c = 0; c < 16; ++c) {
            p[c] = exp2f((s[c] - m_new) * LOG2E);
            l_t += p[c];
        }
        m_run = m_new;

        __syncthreads();  // all S reads of Bs done
        for (int t = tid; t < 1024; t += 256) {
            int row = t >> 4, u = t & 15;
            *(float4*)&Bs[row * 68 + u * 4] =
                *(const float4*)&V[(size_t)(n0 + row) * 64 + u * 4];
        }
        __syncthreads();

        // ---- O += P V ---- (thread accumulates its 16 dims over all 64 cols)
#pragma unroll
        for (int c = 0; c < 64; ++c) {
            // col c is owned by lane with g' = c&3, slot c>>2
            float pc = __shfl_sync(0xffffffffu, p[c >> 2], (lane & ~3) | (c & 3));
            unsigned long long pc2 = pk2(pc, pc);
            const float* vrow = &Bs[c * 68 + g * 4];
#pragma unroll
            for (int u = 0; u < 4; ++u) {
                ulonglong2 v4 = *(const ulonglong2*)(vrow + u * 16);
                accd2[u * 2] = fma2_(pc2, v4.x, accd2[u * 2]);
                accd2[u * 2 + 1] = fma2_(pc2, v4.y, accd2[u * 2 + 1]);
            }
        }
    }

    // ---- epilogue: normalize, write O and row norms ----
    float l = l_t;
    l += __shfl_xor_sync(0xffffffffu, l, 1);
    l += __shfl_xor_sync(0xffffffffu, l, 2);
    float inv = 1.0f / l;

    float nr = 0.f;
#pragma unroll
    for (int u = 0; u < 4; ++u) {
        float2 e0 = up2(accd2[u * 2]);
        float2 e1 = up2(accd2[u * 2 + 1]);
        float o0 = e0.x * inv, o1 = e0.y * inv, o2 = e1.x * inv, o3 = e1.y * inv;
        nr = fmaf(o0, o0, nr);
        nr = fmaf(o1, o1, nr);
        nr = fmaf(o2, o2, nr);
        nr = fmaf(o3, o3, nr);
        *(float4*)&O[(size_t)(m0 + r) * 64 + u * 16 + g * 4] =
            make_float4(o0, o1, o2, o3);
    }
    nr += __shfl_xor_sync(0xffffffffu, nr, 1);
    nr += __shfl_xor_sync(0xffffffffu, nr, 2);
    if (g == 0) nrm[m0 + r] = nr;
}

// ---------------- kernel 3: RBF  out[i,j] = exp(2*dot - |x|^2 - |y|^2) ----------------
// grid (128,128), 256 threads; thread (ty=tid>>4, tx=tid&15) owns rows ty+16a, cols tx+16b.
__global__ __launch_bounds__(256) void rbf_kernel(float* __restrict__ out) {
    __shared__ __align__(16) float Xs[64 * 68];
    __shared__ __align__(16) float Ys[64 * 68];
    __shared__ float snx[64];
    __shared__ float sny[64];

    int tid = threadIdx.x;
    int it = blockIdx.y, jt = blockIdx.x;
    int i0 = it * 64, j0 = jt * 64;

    for (int t = tid; t < 1024; t += 256) {
        int row = t >> 4, u = t & 15;
        *(float4*)&Xs[row * 68 + u * 4] =
            *(const float4*)&g_xatt[(size_t)(i0 + row) * 64 + u * 4];
        *(float4*)&Ys[row * 68 + u * 4] =
            *(const float4*)&g_yatt[(size_t)(j0 + row) * 64 + u * 4];
    }
    if (tid < 64) snx[tid] = g_xnrm[i0 + tid];
    else if (tid < 128) sny[tid - 64] = g_ynrm[j0 + tid - 64];
    __syncthreads();

    int ty = tid >> 4, tx = tid & 15;

    unsigned long long acc[4][4];
#pragma unroll
    for (int a = 0; a < 4; ++a)
#pragma unroll
        for (int bq = 0; bq < 4; ++bq) acc[a][bq] = 0ull;

#pragma unroll
    for (int dd = 0; dd < 64; dd += 4) {
        ulonglong2 xv[4], yv[4];
#pragma unroll
        for (int a = 0; a < 4; ++a)
            xv[a] = *(const ulonglong2*)&Xs[(ty + 16 * a) * 68 + dd];
#pragma unroll
        for (int bq = 0; bq < 4; ++bq)
            yv[bq] = *(const ulonglong2*)&Ys[(tx + 16 * bq) * 68 + dd];
#pragma unroll
        for (int a = 0; a < 4; ++a)
#pragma unroll
            for (int bq = 0; bq < 4; ++bq) {
                acc[a][bq] = fma2_(xv[a].x, yv[bq].x, acc[a][bq]);
                acc[a][bq] = fma2_(xv[a].y, yv[bq].y, acc[a][bq]);
            }
    }

#pragma unroll
    for (int a = 0; a < 4; ++a) {
        int i = i0 + ty + 16 * a;
        float nx = snx[ty + 16 * a];
#pragma unroll
        for (int bq = 0; bq < 4; ++bq) {
            int j = j0 + tx + 16 * bq;
            float2 e = up2(acc[a][bq]);
            float dot = e.x + e.y;
            float arg = 2.0f * dot - nx - sny[tx + 16 * bq];  // = -||xi-yj||^2
            out[(size_t)i * N + j] = exp2f(arg * LOG2E);
        }
    }
}

// ---------------- launch ----------------
extern "C" void kernel_launch(void* const* d_in, const int* in_sizes, int n_in,
                              void* d_out, int out_size) {
    const float* Wq = (const float*)d_in[0];  // rotation_params
    const float* Wk = (const float*)d_in[1];  // entangle_params
    const float* x = (const float*)d_in[2];
    const float* y = (const float*)d_in[3];
    float* out = (float*)d_out;

    proj_kernel<<<(2 * N) / 4, 256>>>(x, y, Wq, Wk);
    attn_kernel<<<256, 256>>>(x, y);
    rbf_kernel<<<dim3(128, 128), 256>>>(out);
}

// round 10
// speedup vs baseline: 4.0006x; 4.0006x over previous
#include <cuda_runtime.h>
#include <cuda_bf16.h>
#include <math_constants.h>
#include <cstdint>

#define N 8192
#define D 64
#define LOG2E 1.4426950408889634f

// ---------------- scratch (static device memory; no allocation) ----------------
__device__ __align__(128) float g_Q[2 * N * D];                       // fp32, 0.125 folded
__device__ __align__(128) float g_Khi[2 * N * D], g_Klo[2 * N * D];   // tf32-valued fp32
__device__ __align__(128) __nv_bfloat16 g_vthi[2 * D * N], g_vtlo[2 * D * N];  // V^T [set][d][n]
__device__ __align__(128) float g_ahi[2 * N * D], g_alo[2 * N * D];   // attention out, tf32-valued
__device__ __align__(128) float g_nrm[2 * N];

// ---------------- helpers ----------------
__device__ __forceinline__ float ex2f(float x) {
    float r;
    asm("ex2.approx.ftz.f32 %0, %1;" : "=f"(r) : "f"(x));
    return r;
}
__device__ __forceinline__ uint32_t f2tf(float v) {
    uint32_t r;
    asm("cvt.rna.tf32.f32 %0, %1;" : "=r"(r) : "f"(v));
    return r;
}
__device__ __forceinline__ float tf32f(float v) { return __uint_as_float(f2tf(v)); }
// pack two f32 -> bf16x2 (lo half = a, hi half = b)
__device__ __forceinline__ uint32_t pkbf2(float a, float b) {
    uint32_t r;
    asm("cvt.rn.bf16x2.f32 %0, %1, %2;" : "=r"(r) : "f"(b), "f"(a));
    return r;
}
__device__ __forceinline__ float bflo_f(uint32_t v) { return __uint_as_float(v << 16); }
__device__ __forceinline__ float bfhi_f(uint32_t v) { return __uint_as_float(v & 0xffff0000u); }

__device__ __forceinline__ void mma_tf(float* c, const uint32_t* a, uint32_t b0, uint32_t b1) {
    asm volatile(
        "mma.sync.aligned.m16n8k8.row.col.f32.tf32.tf32.f32 "
        "{%0,%1,%2,%3},{%4,%5,%6,%7},{%8,%9},{%0,%1,%2,%3};"
        : "+f"(c[0]), "+f"(c[1]), "+f"(c[2]), "+f"(c[3])
        : "r"(a[0]), "r"(a[1]), "r"(a[2]), "r"(a[3]), "r"(b0), "r"(b1));
}
__device__ __forceinline__ void mma_bf(float* c, const uint32_t* a, uint32_t b0, uint32_t b1) {
    asm volatile(
        "mma.sync.aligned.m16n8k16.row.col.f32.bf16.bf16.f32 "
        "{%0,%1,%2,%3},{%4,%5,%6,%7},{%8,%9},{%0,%1,%2,%3};"
        : "+f"(c[0]), "+f"(c[1]), "+f"(c[2]), "+f"(c[3])
        : "r"(a[0]), "r"(a[1]), "r"(a[2]), "r"(a[3]), "r"(b0), "r"(b1));
}
__device__ __forceinline__ uint32_t smem_u32(const void* p) {
    uint32_t a;
    asm("{ .reg .u64 t; cvta.to.shared.u64 t, %1; cvt.u32.u64 %0, t; }" : "=r"(a) : "l"(p));
    return a;
}
__device__ __forceinline__ void cpa16(uint32_t s, const void* g) {
    asm volatile("cp.async.cg.shared.global [%0], [%1], 16;" :: "r"(s), "l"(g));
}
__device__ __forceinline__ void cp_commit() { asm volatile("cp.async.commit_group;" ::: "memory"); }
__device__ __forceinline__ void cp_wait0() { asm volatile("cp.async.wait_group 0;" ::: "memory"); }
__device__ __forceinline__ void cp_wait1() { asm volatile("cp.async.wait_group 1;" ::: "memory"); }

// fp32 64x64 tile -> smem (float stride 68) via cp.async
__device__ __forceinline__ void cpa_k(uint32_t dst, const float* g, int tid) {
#pragma unroll
    for (int ci = tid; ci < 1024; ci += 256) {
        int row = ci >> 4, u = ci & 15;
        cpa16(dst + row * 272 + u * 16, g + row * 64 + u * 4);
    }
}
// bf16 V^T 64(d)x64(key) tile (global row stride N) -> smem (bf16 stride 72)
__device__ __forceinline__ void cpa_v(uint32_t dst, const __nv_bfloat16* g, int tid) {
#pragma unroll
    for (int ci = tid; ci < 512; ci += 256) {
        int row = ci >> 3, u = ci & 7;
        cpa16(dst + row * 144 + u * 16, g + (size_t)row * N + u * 8);
    }
}
// fp32 128x64 tile -> smem stride 68, plain loads
__device__ __forceinline__ void ld128(float* s, const float* g, int tid) {
#pragma unroll
    for (int ci = tid; ci < 2048; ci += 256) {
        int row = ci >> 4, u = ci & 15;
        *(float4*)(s + row * 68 + u * 4) = *(const float4*)(g + row * 64 + u * 4);
    }
}

// ---------------- kernel 1: projections + splits ----------------
__global__ __launch_bounds__(256) void proj_kernel(const float* __restrict__ x,
                                                   const float* __restrict__ y,
                                                   const float* __restrict__ Wq,
                                                   const float* __restrict__ Wk) {
    __shared__ float sW[2][64][65];
    __shared__ float sIn[4][64];
    int tid = threadIdx.x;
    int base = blockIdx.x * 4;
    int set = base < N ? 0 : 1;
    int r0 = set ? base - N : base;
    const float* src = (set ? y : x) + (size_t)r0 * D;

    for (int idx = tid; idx < 4096; idx += 256) {
        sW[0][idx >> 6][idx & 63] = Wq[idx];
        sW[1][idx >> 6][idx & 63] = Wk[idx];
    }
    int j = tid & 63, rl = tid >> 6;
    float v_in = src[tid];
    sIn[rl][j] = v_in;
    {   // V^T bf16 2-term split: element (row r0+rl, dim j) -> [set][j][row]
        size_t o = (size_t)set * D * N + (size_t)j * N + (r0 + rl);
        __nv_bfloat16 h = __float2bfloat16(v_in);
        g_vthi[o] = h;
        g_vtlo[o] = __float2bfloat16(v_in - __bfloat162float(h));
    }
    __syncthreads();

    float fq = 0.f, fk = 0.f;
#pragma unroll
    for (int k = 0; k < 64; ++k) {
        float v = sIn[rl][k];
        fq = fmaf(v, sW[0][k][j], fq);
        fk = fmaf(v, sW[1][k][j], fk);
    }
    fq *= 0.125f;  // fold 1/sqrt(64)
    size_t o = (size_t)set * N * D + (size_t)(r0 + rl) * D + j;
    g_Q[o] = fq;
    float kh = tf32f(fk);
    g_Khi[o] = kh;
    g_Klo[o] = tf32f(fk - kh);
}

// ---------------- kernel 2: flash attention via mma.sync ----------------
// 128 blocks (2 sets x 64 q-tiles of 128 rows), 256 threads = 8 warps x 16 q-rows.
// Key tile = 64. S: tf32 m16n8k8, 2-term split (3 products). PV: bf16 m16n8k16,
// P/V 2-term split (3 products), online softmax in fragments.
#define SQ 0
#define SKH 34816
#define SKL 69632
#define SVH 104448
#define SVL 122880
#define ATTN_SMEM 141312

__global__ __launch_bounds__(256, 1) void attn_kernel() {
    extern __shared__ __align__(16) char sm[];
    uint32_t sb = smem_u32(sm);
    int tid = threadIdx.x, wid = tid >> 5, lane = tid & 31;
    int g = lane >> 2, tg = lane & 3;
    int set = blockIdx.x >> 6;
    int m0 = (int)(blockIdx.x & 63) * 128;

    const float* Qg = g_Q + (size_t)set * N * D + (size_t)m0 * D;
    const float* Khg = g_Khi + (size_t)set * N * D;
    const float* Klg = g_Klo + (size_t)set * N * D;
    const __nv_bfloat16* Vhg = g_vthi + (size_t)set * D * N;
    const __nv_bfloat16* Vlg = g_vtlo + (size_t)set * D * N;

    ld128((float*)(sm + SQ), Qg, tid);
    // prefetch tile 0
    cpa_k(sb + SKH, Khg, tid);
    cpa_k(sb + SKL, Klg, tid);
    cpa_v(sb + SVH, Vhg, tid);
    cpa_v(sb + SVL, Vlg, tid);
    cp_commit();
    __syncthreads();

    // Q fragments (row-major A, m16k8): split to tf32 hi/lo once
    uint32_t qh[8][4], ql[8][4];
    {
        const float* sQ = (const float*)(sm + SQ);
        int r0 = wid * 16 + g;
#pragma unroll
        for (int ks = 0; ks < 8; ++ks) {
            float v0 = sQ[r0 * 68 + ks * 8 + tg];
            float v1 = sQ[(r0 + 8) * 68 + ks * 8 + tg];
            float v2 = sQ[r0 * 68 + ks * 8 + tg + 4];
            float v3 = sQ[(r0 + 8) * 68 + ks * 8 + tg + 4];
            qh[ks][0] = f2tf(v0); ql[ks][0] = f2tf(v0 - __uint_as_float(qh[ks][0]));
            qh[ks][1] = f2tf(v1); ql[ks][1] = f2tf(v1 - __uint_as_float(qh[ks][1]));
            qh[ks][2] = f2tf(v2); ql[ks][2] = f2tf(v2 - __uint_as_float(qh[ks][2]));
            qh[ks][3] = f2tf(v3); ql[ks][3] = f2tf(v3 - __uint_as_float(qh[ks][3]));
        }
    }

    float o[8][4];
#pragma unroll
    for (int db = 0; db < 8; ++db)
#pragma unroll
        for (int q = 0; q < 4; ++q) o[db][q] = 0.f;
    float mr0 = -CUDART_INF_F, mr1 = -CUDART_INF_F;
    float l0 = 0.f, l1 = 0.f;

#pragma unroll 1
    for (int kt = 0; kt < 128; ++kt) {
        int b = kt & 1;
        if (kt < 127) {
            size_t ko = (size_t)(kt + 1) * 64;
            cpa_k(sb + SKH + (b ^ 1) * 17408, Khg + ko * D, tid);
            cpa_k(sb + SKL + (b ^ 1) * 17408, Klg + ko * D, tid);
            cpa_v(sb + SVH + (b ^ 1) * 9216, Vhg + ko, tid);
            cpa_v(sb + SVL + (b ^ 1) * 9216, Vlg + ko, tid);
            cp_commit();
            cp_wait1();
        } else {
            cp_wait0();
        }
        __syncthreads();
        const float* KH = (const float*)(sm + SKH + b * 17408);
        const float* KL = (const float*)(sm + SKL + b * 17408);
        const __nv_bfloat16* VH = (const __nv_bfloat16*)(sm + SVH + b * 9216);
        const __nv_bfloat16* VL = (const __nv_bfloat16*)(sm + SVL + b * 9216);

        // ---- S = Q K^T ----
        float sc[8][4];
#pragma unroll
        for (int nb = 0; nb < 8; ++nb)
#pragma unroll
            for (int q = 0; q < 4; ++q) sc[nb][q] = 0.f;
#pragma unroll
        for (int nb = 0; nb < 8; ++nb) {
            int kr = (nb * 8 + g) * 68;
#pragma unroll
            for (int ks = 0; ks < 8; ++ks) {
                uint32_t bh0 = __float_as_uint(KH[kr + ks * 8 + tg]);
                uint32_t bh1 = __float_as_uint(KH[kr + ks * 8 + tg + 4]);
                uint32_t bl0 = __float_as_uint(KL[kr + ks * 8 + tg]);
                uint32_t bl1 = __float_as_uint(KL[kr + ks * 8 + tg + 4]);
                mma_tf(sc[nb], qh[ks], bh0, bh1);
                mma_tf(sc[nb], qh[ks], bl0, bl1);
                mma_tf(sc[nb], ql[ks], bh0, bh1);
            }
        }

        // ---- online softmax ----
        float mt0 = sc[0][0], mt1 = sc[0][2];
#pragma unroll
        for (int nb = 0; nb < 8; ++nb) {
            mt0 = fmaxf(mt0, fmaxf(sc[nb][0], sc[nb][1]));
            mt1 = fmaxf(mt1, fmaxf(sc[nb][2], sc[nb][3]));
        }
        mt0 = fmaxf(mt0, __shfl_xor_sync(0xffffffffu, mt0, 1));
        mt0 = fmaxf(mt0, __shfl_xor_sync(0xffffffffu, mt0, 2));
        mt1 = fmaxf(mt1, __shfl_xor_sync(0xffffffffu, mt1, 1));
        mt1 = fmaxf(mt1, __shfl_xor_sync(0xffffffffu, mt1, 2));
        float mn0 = fmaxf(mr0, mt0), mn1 = fmaxf(mr1, mt1);
        float s0 = ex2f((mr0 - mn0) * LOG2E);
        float s1 = ex2f((mr1 - mn1) * LOG2E);
        l0 *= s0; l1 *= s1;
#pragma unroll
        for (int db = 0; db < 8; ++db) {
            o[db][0] *= s0; o[db][1] *= s0;
            o[db][2] *= s1; o[db][3] *= s1;
        }
        mr0 = mn0; mr1 = mn1;
        uint32_t ph[8][2], pl[8][2];
#pragma unroll
        for (int nb = 0; nb < 8; ++nb) {
            float p0 = ex2f((sc[nb][0] - mn0) * LOG2E);
            float p1 = ex2f((sc[nb][1] - mn0) * LOG2E);
            float p2 = ex2f((sc[nb][2] - mn1) * LOG2E);
            float p3 = ex2f((sc[nb][3] - mn1) * LOG2E);
            l0 += p0 + p1; l1 += p2 + p3;
            uint32_t h0 = pkbf2(p0, p1), h1 = pkbf2(p2, p3);
            ph[nb][0] = h0; pl[nb][0] = pkbf2(p0 - bflo_f(h0), p1 - bfhi_f(h0));
            ph[nb][1] = h1; pl[nb][1] = pkbf2(p2 - bflo_f(h1), p3 - bfhi_f(h1));
        }

        // ---- O += P V  (bf16 m16n8k16, 3 products) ----
#pragma unroll
        for (int j = 0; j < 4; ++j) {
            uint32_t ah[4] = {ph[2 * j][0], ph[2 * j][1], ph[2 * j + 1][0], ph[2 * j + 1][1]};
            uint32_t al[4] = {pl[2 * j][0], pl[2 * j][1], pl[2 * j + 1][0], pl[2 * j + 1][1]};
#pragma unroll
            for (int db = 0; db < 8; ++db) {
                int dr = (db * 8 + g) * 72 + j * 16 + 2 * tg;
                uint32_t bh0 = *(const uint32_t*)(VH + dr);
                uint32_t bh1 = *(const uint32_t*)(VH + dr + 8);
                uint32_t bl0 = *(const uint32_t*)(VL + dr);
                uint32_t bl1 = *(const uint32_t*)(VL + dr + 8);
                mma_bf(o[db], ah, bh0, bh1);
                mma_bf(o[db], ah, bl0, bl1);
                mma_bf(o[db], al, bh0, bh1);
            }
        }
        __syncthreads();
    }

    // ---- epilogue ----
    l0 += __shfl_xor_sync(0xffffffffu, l0, 1);
    l0 += __shfl_xor_sync(0xffffffffu, l0, 2);
    l1 += __shfl_xor_sync(0xffffffffu, l1, 1);
    l1 += __shfl_xor_sync(0xffffffffu, l1, 2);
    float i0 = 1.0f / l0, i1 = 1.0f / l1;
    int r0 = m0 + wid * 16 + g, r1 = r0 + 8;
    size_t base0 = ((size_t)set * N + r0) * D, base1 = ((size_t)set * N + r1) * D;
    float nr0 = 0.f, nr1 = 0.f;
#pragma unroll
    for (int db = 0; db < 8; ++db) {
        float v0 = o[db][0] * i0, v1 = o[db][1] * i0;
        float v2 = o[db][2] * i1, v3 = o[db][3] * i1;
        nr0 = fmaf(v0, v0, fmaf(v1, v1, nr0));
        nr1 = fmaf(v2, v2, fmaf(v3, v3, nr1));
        int c = db * 8 + 2 * tg;
        float h0 = tf32f(v0), h1 = tf32f(v1), h2 = tf32f(v2), h3 = tf32f(v3);
        *(float2*)&g_ahi[base0 + c] = make_float2(h0, h1);
        *(float2*)&g_alo[base0 + c] = make_float2(tf32f(v0 - h0), tf32f(v1 - h1));
        *(float2*)&g_ahi[base1 + c] = make_float2(h2, h3);
        *(float2*)&g_alo[base1 + c] = make_float2(tf32f(v2 - h2), tf32f(v3 - h3));
    }
    nr0 += __shfl_xor_sync(0xffffffffu, nr0, 1);
    nr0 += __shfl_xor_sync(0xffffffffu, nr0, 2);
    nr1 += __shfl_xor_sync(0xffffffffu, nr1, 1);
    nr1 += __shfl_xor_sync(0xffffffffu, nr1, 2);
    if (tg == 0) {
        g_nrm[set * N + r0] = nr0;
        g_nrm[set * N + r1] = nr1;
    }
}

// ---------------- kernel 3: RBF via mma.sync ----------------
// 4096 blocks: 128x128 tile, 8 warps x 16 i-rows. tf32 2-term dots; exp epilogue.
#define RXH 0
#define RXL 34816
#define RYH 69632
#define RYL 104448
#define RNX 139264
#define RNY 139776
#define RBF_SMEM 140288

__global__ __launch_bounds__(256, 1) void rbf_kernel(float* __restrict__ out) {
    extern __shared__ __align__(16) char sm[];
    int tid = threadIdx.x, wid = tid >> 5, lane = tid & 31;
    int g = lane >> 2, tg = lane & 3;
    int i0 = blockIdx.y * 128, j0 = blockIdx.x * 128;

    ld128((float*)(sm + RXH), g_ahi + (size_t)i0 * D, tid);
    ld128((float*)(sm + RXL), g_alo + (size_t)i0 * D, tid);
    ld128((float*)(sm + RYH), g_ahi + ((size_t)N + j0) * D, tid);
    ld128((float*)(sm + RYL), g_alo + ((size_t)N + j0) * D, tid);
    if (tid < 128) {
        ((float*)(sm + RNX))[tid] = g_nrm[i0 + tid];
        ((float*)(sm + RNY))[tid] = g_nrm[N + j0 + tid];
    }
    __syncthreads();

    const float* XH = (const float*)(sm + RXH);
    const float* XL = (const float*)(sm + RXL);
    const float* YH = (const float*)(sm + RYH);
    const float* YL = (const float*)(sm + RYL);

    uint32_t ah[8][4], al[8][4];
    int r0 = wid * 16 + g;
#pragma unroll
    for (int ks = 0; ks < 8; ++ks) {
        ah[ks][0] = __float_as_uint(XH[r0 * 68 + ks * 8 + tg]);
        ah[ks][1] = __float_as_uint(XH[(r0 + 8) * 68 + ks * 8 + tg]);
        ah[ks][2] = __float_as_uint(XH[r0 * 68 + ks * 8 + tg + 4]);
        ah[ks][3] = __float_as_uint(XH[(r0 + 8) * 68 + ks * 8 + tg + 4]);
        al[ks][0] = __float_as_uint(XL[r0 * 68 + ks * 8 + tg]);
        al[ks][1] = __float_as_uint(XL[(r0 + 8) * 68 + ks * 8 + tg]);
        al[ks][2] = __float_as_uint(XL[r0 * 68 + ks * 8 + tg + 4]);
        al[ks][3] = __float_as_uint(XL[(r0 + 8) * 68 + ks * 8 + tg + 4]);
    }

    float c[16][4];
#pragma unroll
    for (int nb = 0; nb < 16; ++nb)
#pragma unroll
        for (int q = 0; q < 4; ++q) c[nb][q] = 0.f;

#pragma unroll
    for (int nb = 0; nb < 16; ++nb) {
        int yr = (nb * 8 + g) * 68;
#pragma unroll
        for (int ks = 0; ks < 8; ++ks) {
            uint32_t bh0 = __float_as_uint(YH[yr + ks * 8 + tg]);
            uint32_t bh1 = __float_as_uint(YH[yr + ks * 8 + tg + 4]);
            uint32_t bl0 = __float_as_uint(YL[yr + ks * 8 + tg]);
            uint32_t bl1 = __float_as_uint(YL[yr + ks * 8 + tg + 4]);
            mma_tf(c[nb], ah[ks], bh0, bh1);
            mma_tf(c[nb], ah[ks], bl0, bl1);
            mma_tf(c[nb], al[ks], bh0, bh1);
        }
    }

    const float* snx = (const float*)(sm + RNX);
    const float* sny = (const float*)(sm + RNY);
    float nx0 = snx[wid * 16 + g], nx1 = snx[wid * 16 + g + 8];
    float* out0 = out + (size_t)(i0 + wid * 16 + g) * N + j0;
    float* out1 = out0 + (size_t)8 * N;
#pragma unroll
    for (int nb = 0; nb < 16; ++nb) {
        int col = nb * 8 + 2 * tg;
        float ny0 = sny[col], ny1 = sny[col + 1];
        float a0 = fmaf(2.f, c[nb][0], -nx0 - ny0);
        float a1 = fmaf(2.f, c[nb][1], -nx0 - ny1);
        float a2 = fmaf(2.f, c[nb][2], -nx1 - ny0);
        float a3 = fmaf(2.f, c[nb][3], -nx1 - ny1);
        *(float2*)(out0 + col) = make_float2(ex2f(a0 * LOG2E), ex2f(a1 * LOG2E));
        *(float2*)(out1 + col) = make_float2(ex2f(a2 * LOG2E), ex2f(a3 * LOG2E));
    }
}

// ---------------- launch ----------------
extern "C" void kernel_launch(void* const* d_in, const int* in_sizes, int n_in,
                              void* d_out, int out_size) {
    const float* Wq = (const float*)d_in[0];  // rotation_params
    const float* Wk = (const float*)d_in[1];  // entangle_params
    const float* x = (const float*)d_in[2];
    const float* y = (const float*)d_in[3];
    float* out = (float*)d_out;

    cudaFuncSetAttribute(attn_kernel, cudaFuncAttributeMaxDynamicSharedMemorySize, ATTN_SMEM);
    cudaFuncSetAttribute(rbf_kernel, cudaFuncAttributeMaxDynamicSharedMemorySize, RBF_SMEM);

    proj_kernel<<<(2 * N) / 4, 256>>>(x, y, Wq, Wk);
    attn_kernel<<<128, 256, ATTN_SMEM>>>();
    rbf_kernel<<<dim3(64, 64), 256, RBF_SMEM>>>(out);
}